// round 3
// baseline (speedup 1.0000x reference)
#include <cuda_runtime.h>
#include <math.h>

#define TILE_B   32
#define NCHUNK   8
#define NTHREADS 256
#define NPIX     784
#define NCLS     10
#define PIX_PER_CHUNK 98   // 784 / 8

// smem layout (dynamic):
//   wbuf[784][20] : interleaved (ws, wc) per class, float4-friendly rows of 80B
//   part[8][32][10]: per-chunk partial logits
#define SMEM_WBUF_FLOATS (NPIX * 2 * NCLS)          // 15680
#define SMEM_PART_FLOATS (NCHUNK * TILE_B * NCLS)   // 2560
#define SMEM_BYTES ((SMEM_WBUF_FLOATS + SMEM_PART_FLOATS) * 4)  // 72960

__global__ __launch_bounds__(NTHREADS, 2)
void quanv_fused_kernel(const float* __restrict__ x,
                        const float* __restrict__ params,
                        const float* __restrict__ w,
                        const float* __restrict__ bias,
                        float* __restrict__ out,
                        int B, int depth)
{
    extern __shared__ float sm[];
    float* wbuf = sm;                       // [784][20]
    float* part = sm + SMEM_WBUF_FLOATS;    // [8][32][10]
    __shared__ float ab[8];                 // ab[q] = beta_q (cos coeff), ab[4+q] = alpha_q (sin coeff)

    const int tid = threadIdx.x;

    // ---- Phase 0: alpha/beta per qubit via exact 2x2 complex simulation ----
    // z(theta) = alpha*sin(theta) + beta*cos(theta); evaluate at theta=0 (beta)
    // and theta=pi/2 (alpha).
    if (tid < 8) {
        const int q     = tid & 3;
        const int which = tid >> 2;                 // 0 -> theta=0, 1 -> theta=pi/2
        const float th  = which ? 1.5707963267948966f : 0.0f;
        float ar = cosf(0.5f * th), ai = 0.0f;
        float br = sinf(0.5f * th), bi = 0.0f;
        for (int d = 0; d < depth; d++) {
            const float rz1 = params[d * 12 + q * 3 + 0];
            const float ry  = params[d * 12 + q * 3 + 1];
            const float rz2 = params[d * 12 + q * 3 + 2];
            // a *= exp(-i rz1/2); b *= exp(+i rz1/2)
            float p1r = cosf(0.5f * rz1), p1i = -sinf(0.5f * rz1);
            float nar = ar * p1r - ai * p1i, nai = ar * p1i + ai * p1r;
            float nbr = br * p1r + bi * p1i, nbi = bi * p1r - br * p1i;
            ar = nar; ai = nai; br = nbr; bi = nbi;
            // Ry rotation (real)
            const float c = cosf(0.5f * ry), s = sinf(0.5f * ry);
            nar = c * ar - s * br; nai = c * ai - s * bi;
            nbr = s * ar + c * br; nbi = s * ai + c * bi;
            ar = nar; ai = nai; br = nbr; bi = nbi;
            // a *= exp(-i rz2/2); b *= exp(+i rz2/2)
            const float p2r = cosf(0.5f * rz2), p2i = -sinf(0.5f * rz2);
            nar = ar * p2r - ai * p2i; nai = ar * p2i + ai * p2r;
            nbr = br * p2r + bi * p2i; nbi = bi * p2r - br * p2i;
            ar = nar; ai = nai; br = nbr; bi = nbi;
        }
        ab[which * 4 + q] = (ar * ar + ai * ai) - (br * br + bi * bi);
    }
    __syncthreads();

    // ---- Phase 1: fold w (patch-order) into pixel-order smem with alpha/beta ----
    // pixel (r,cc): q = (r&1)*2 + (cc&1), feature f = ((r>>1)*14 + (cc>>1))*4 + q
    for (int idx = tid; idx < NPIX * NCLS; idx += NTHREADS) {
        const int pix = idx / NCLS;
        const int c   = idx - pix * NCLS;
        const int r   = pix / 28;
        const int cc  = pix - r * 28;
        const int q   = ((r & 1) << 1) + (cc & 1);
        const int f   = (((r >> 1) * 14 + (cc >> 1)) << 2) + q;
        const float wv = w[c * NPIX + f];
        wbuf[pix * 20 + 2 * c]     = wv * ab[4 + q];  // sin coefficient
        wbuf[pix * 20 + 2 * c + 1] = wv * ab[q];      // cos coefficient
    }
    __syncthreads();

    // ---- Phase 2: main accumulation ----
    // warp = 32 images at the SAME pixel -> wbuf reads are warp-uniform (broadcast LDS).
    const int img   = tid & (TILE_B - 1);
    const int chunk = tid >> 5;
    const int b     = blockIdx.x * TILE_B + img;

    float acc[NCLS];
#pragma unroll
    for (int c = 0; c < NCLS; c++) acc[c] = 0.0f;

    if (b < B) {
        const float* __restrict__ xrow = x + (size_t)b * NPIX;
        const int p0 = chunk * PIX_PER_CHUNK;
#pragma unroll 2
        for (int k = 0; k < PIX_PER_CHUNK; k++) {
            const int pix = p0 + k;
            const float xv = __ldg(xrow + pix);
            float s, co;
            __sincosf(xv, &s, &co);
            const float4* wp = reinterpret_cast<const float4*>(wbuf + pix * 20);
#pragma unroll
            for (int j = 0; j < 5; j++) {
                const float4 v = wp[j];
                acc[2 * j]     += v.x * s + v.y * co;
                acc[2 * j + 1] += v.z * s + v.w * co;
            }
        }
    }

    // ---- Phase 3: cross-chunk reduce + log-softmax ----
    float* my = part + (chunk * TILE_B + img) * NCLS;
#pragma unroll
    for (int c = 0; c < NCLS; c++) my[c] = acc[c];
    __syncthreads();

    if (tid < TILE_B) {
        const int b2 = blockIdx.x * TILE_B + tid;
        if (b2 < B) {
            float l[NCLS];
#pragma unroll
            for (int c = 0; c < NCLS; c++) {
                float sum = bias[c];
#pragma unroll
                for (int ch = 0; ch < NCHUNK; ch++)
                    sum += part[(ch * TILE_B + tid) * NCLS + c];
                l[c] = sum;
            }
            float m = l[0];
#pragma unroll
            for (int c = 1; c < NCLS; c++) m = fmaxf(m, l[c]);
            float se = 0.0f;
#pragma unroll
            for (int c = 0; c < NCLS; c++) se += expf(l[c] - m);
            const float lse = m + logf(se);
            float* orow = out + (size_t)b2 * NCLS;
#pragma unroll
            for (int c = 0; c < NCLS; c++) orow[c] = l[c] - lse;
        }
    }
}

extern "C" void kernel_launch(void* const* d_in, const int* in_sizes, int n_in,
                              void* d_out, int out_size)
{
    const float* x      = (const float*)d_in[0];
    const float* params = (const float*)d_in[1];
    const float* w      = (const float*)d_in[2];
    const float* bias   = (const float*)d_in[3];
    float* out          = (float*)d_out;

    const int B     = in_sizes[0] / NPIX;
    const int depth = in_sizes[1] / 12;

    cudaFuncSetAttribute(quanv_fused_kernel,
                         cudaFuncAttributeMaxDynamicSharedMemorySize, SMEM_BYTES);

    const int grid = (B + TILE_B - 1) / TILE_B;
    quanv_fused_kernel<<<grid, NTHREADS, SMEM_BYTES>>>(x, params, w, bias, out, B, depth);
}

// round 4
// speedup vs baseline: 1.2611x; 1.2611x over previous
#include <cuda_runtime.h>
#include <math.h>

#define TILE_B   32
#define NCHUNK   8
#define NTHREADS 256
#define NPIX     784
#define NCLS     10
#define PIX_PER_CHUNK 98   // 784 / 8

// smem layout (dynamic, floats):
//   wbuf  [784][20]        : interleaved (ws, wc) per class, 80B rows (16B aligned)
//   xstg  [8][32][33]      : per-warp transposed x staging tile (+1 pad, conflict-free)
//   part  [8][32][10]      : per-chunk partial logits
#define WBUF_F (NPIX * 2 * NCLS)            // 15680
#define XSTG_F (NCHUNK * 32 * 33)           // 8448
#define PART_F (NCHUNK * TILE_B * NCLS)     // 2560
#define SMEM_BYTES ((WBUF_F + XSTG_F + PART_F) * 4)   // 106752

__device__ __forceinline__ unsigned long long pack2(float lo, float hi) {
    unsigned long long r;
    asm("mov.b64 %0, {%1, %2};" : "=l"(r) : "f"(lo), "f"(hi));
    return r;
}
__device__ __forceinline__ unsigned long long ffma2(unsigned long long a,
                                                    unsigned long long b,
                                                    unsigned long long c) {
    unsigned long long d;
    asm("fma.rn.f32x2 %0, %1, %2, %3;" : "=l"(d) : "l"(a), "l"(b), "l"(c));
    return d;
}
__device__ __forceinline__ float2 unpack2(unsigned long long v) {
    float lo, hi;
    asm("mov.b64 {%0, %1}, %2;" : "=f"(lo), "=f"(hi) : "l"(v));
    return make_float2(lo, hi);
}

__global__ __launch_bounds__(NTHREADS, 2)
void quanv_fused_kernel(const float* __restrict__ x,
                        const float* __restrict__ params,
                        const float* __restrict__ w,
                        const float* __restrict__ bias,
                        float* __restrict__ out,
                        int B, int depth)
{
    extern __shared__ float sm[];
    float* wbuf = sm;                      // [784][20]
    float* xstg = sm + WBUF_F;             // [8][32][33]
    float* part = sm + WBUF_F + XSTG_F;    // [8][32][10]
    __shared__ float ab[8];                // ab[q]=beta_q (cos), ab[4+q]=alpha_q (sin)

    const int tid  = threadIdx.x;
    const int lane = tid & 31;
    const int chunk = tid >> 5;

    // ---- Phase 0: alpha/beta per qubit via exact 2x2 complex simulation ----
    if (tid < 8) {
        const int q     = tid & 3;
        const int which = tid >> 2;
        float ar = which ? 0.70710678118654752f : 1.0f, ai = 0.0f;
        float br = which ? 0.70710678118654752f : 0.0f, bi = 0.0f;
        for (int d = 0; d < depth; d++) {
            const float rz1 = params[d * 12 + q * 3 + 0];
            const float ry  = params[d * 12 + q * 3 + 1];
            const float rz2 = params[d * 12 + q * 3 + 2];
            float p1i, p1r; __sincosf(0.5f * rz1, &p1i, &p1r); p1i = -p1i;
            float nar = ar * p1r - ai * p1i, nai = ar * p1i + ai * p1r;
            float nbr = br * p1r + bi * p1i, nbi = bi * p1r - br * p1i;
            ar = nar; ai = nai; br = nbr; bi = nbi;
            float s, c; __sincosf(0.5f * ry, &s, &c);
            nar = c * ar - s * br; nai = c * ai - s * bi;
            nbr = s * ar + c * br; nbi = s * ai + c * bi;
            ar = nar; ai = nai; br = nbr; bi = nbi;
            float p2i, p2r; __sincosf(0.5f * rz2, &p2i, &p2r); p2i = -p2i;
            nar = ar * p2r - ai * p2i; nai = ar * p2i + ai * p2r;
            nbr = br * p2r + bi * p2i; nbi = bi * p2r - br * p2i;
            ar = nar; ai = nai; br = nbr; bi = nbi;
        }
        ab[which * 4 + q] = (ar * ar + ai * ai) - (br * br + bi * bi);
    }
    __syncthreads();

    // ---- Phase 1: fold w (patch-order) into pixel-order smem with alpha/beta ----
    for (int idx = tid; idx < NPIX * NCLS; idx += NTHREADS) {
        const int pix = idx / NCLS;
        const int c   = idx - pix * NCLS;
        const int r   = pix / 28;
        const int cc  = pix - r * 28;
        const int q   = ((r & 1) << 1) + (cc & 1);
        const int f   = (((r >> 1) * 14 + (cc >> 1)) << 2) + q;
        const float wv = w[c * NPIX + f];
        wbuf[pix * 20 + 2 * c]     = wv * ab[4 + q];  // sin coefficient
        wbuf[pix * 20 + 2 * c + 1] = wv * ab[q];      // cos coefficient
    }
    __syncthreads();

    // ---- Phase 2: main accumulation ----
    // warp = 32 images, chunk of 98 pixels. x is staged in 32-pixel tiles through
    // warp-private smem so global loads are lane-contiguous (1 line per LDG).
    const int b0 = blockIdx.x * TILE_B;
    const int bmax = B - 1 - b0;           // clamp for partial last tile
    const int p0 = chunk * PIX_PER_CHUNK;
    const float* __restrict__ xch = x + (size_t)b0 * NPIX + p0;
    float* xsw = xstg + chunk * (32 * 33);

    unsigned long long acc[NCLS];
#pragma unroll
    for (int c = 0; c < NCLS; c++) acc[c] = 0ull;

    for (int tb = 0; tb < 96; tb += 32) {
        // stage: image i, pixel (p0+tb+lane) -> xsw[lane*33 + i]
#pragma unroll
        for (int i = 0; i < 32; i++) {
            const int ri = (i <= bmax) ? i : (bmax < 0 ? 0 : bmax);
            xsw[lane * 33 + i] = xch[(size_t)ri * NPIX + tb + lane];
        }
        __syncwarp();
#pragma unroll 4
        for (int k = 0; k < 32; k++) {
            const float xv = xsw[k * 33 + lane];
            float s, co;
            __sincosf(xv, &s, &co);
            const unsigned long long sc = pack2(s, co);
            const ulonglong2* __restrict__ wp =
                reinterpret_cast<const ulonglong2*>(wbuf + (p0 + tb + k) * 20);
#pragma unroll
            for (int j = 0; j < 5; j++) {
                const ulonglong2 v = wp[j];
                acc[2 * j]     = ffma2(v.x, sc, acc[2 * j]);
                acc[2 * j + 1] = ffma2(v.y, sc, acc[2 * j + 1]);
            }
        }
        __syncwarp();
    }
    // epilogue: 2 leftover pixels (98 = 3*32 + 2), direct (uncoalesced, tiny)
    if (lane <= bmax) {
        const float* __restrict__ xrow = x + (size_t)(b0 + lane) * NPIX + p0;
#pragma unroll
        for (int e = 0; e < 2; e++) {
            const float xv = xrow[96 + e];
            float s, co;
            __sincosf(xv, &s, &co);
            const unsigned long long sc = pack2(s, co);
            const ulonglong2* __restrict__ wp =
                reinterpret_cast<const ulonglong2*>(wbuf + (p0 + 96 + e) * 20);
#pragma unroll
            for (int j = 0; j < 5; j++) {
                const ulonglong2 v = wp[j];
                acc[2 * j]     = ffma2(v.x, sc, acc[2 * j]);
                acc[2 * j + 1] = ffma2(v.y, sc, acc[2 * j + 1]);
            }
        }
    }

    // ---- Phase 3: cross-chunk reduce + log-softmax ----
    float* my = part + (chunk * TILE_B + lane) * NCLS;
#pragma unroll
    for (int c = 0; c < NCLS; c++) {
        const float2 f2 = unpack2(acc[c]);
        my[c] = f2.x + f2.y;
    }
    __syncthreads();

    if (tid < TILE_B) {
        const int b2 = b0 + tid;
        if (b2 < B) {
            float l[NCLS];
#pragma unroll
            for (int c = 0; c < NCLS; c++) {
                float sum = bias[c];
#pragma unroll
                for (int ch = 0; ch < NCHUNK; ch++)
                    sum += part[(ch * TILE_B + tid) * NCLS + c];
                l[c] = sum;
            }
            float m = l[0];
#pragma unroll
            for (int c = 1; c < NCLS; c++) m = fmaxf(m, l[c]);
            float se = 0.0f;
#pragma unroll
            for (int c = 0; c < NCLS; c++) se += expf(l[c] - m);
            const float lse = m + logf(se);
            float* orow = out + (size_t)b2 * NCLS;
#pragma unroll
            for (int c = 0; c < NCLS; c++) orow[c] = l[c] - lse;
        }
    }
}

extern "C" void kernel_launch(void* const* d_in, const int* in_sizes, int n_in,
                              void* d_out, int out_size)
{
    const float* x      = (const float*)d_in[0];
    const float* params = (const float*)d_in[1];
    const float* w      = (const float*)d_in[2];
    const float* bias   = (const float*)d_in[3];
    float* out          = (float*)d_out;

    const int B     = in_sizes[0] / NPIX;
    const int depth = in_sizes[1] / 12;

    cudaFuncSetAttribute(quanv_fused_kernel,
                         cudaFuncAttributeMaxDynamicSharedMemorySize, SMEM_BYTES);

    const int grid = (B + TILE_B - 1) / TILE_B;
    quanv_fused_kernel<<<grid, NTHREADS, SMEM_BYTES>>>(x, params, w, bias, out, B, depth);
}

// round 9
// speedup vs baseline: 1.7912x; 1.4203x over previous
#include <cuda_runtime.h>
#include <math.h>

#define TILE_B   32
#define NTHREADS 512
#define NCHUNK   16
#define NPIX     784
#define NCLS     10
#define PPC      49        // pixels per chunk (784 / 16)
#define TP       8         // staging tile pixels
#define NTILE    6         // 6*8 = 48, +1 leftover pixel

// smem layout (dynamic, floats):
//   wbuf [784][20]      : interleaved (ws, wc) per class, 80B rows  (62720 B)
//   xstg [16][8][36]    : per-warp staging, pad-36 (conflict-free)  (18432 B)
// after main loop, wbuf region is reused for:
//   part [16][32][10] (5120 f) then red [32][10] (320 f)
#define WBUF_F (NPIX * 2 * NCLS)        // 15680
#define XSTG_F (NCHUNK * TP * 36)       // 4608
#define SMEM_BYTES ((WBUF_F + XSTG_F) * 4)   // 81152

__device__ __forceinline__ unsigned long long pack2(float lo, float hi) {
    unsigned long long r;
    asm("mov.b64 %0, {%1, %2};" : "=l"(r) : "f"(lo), "f"(hi));
    return r;
}
__device__ __forceinline__ unsigned long long ffma2(unsigned long long a,
                                                    unsigned long long b,
                                                    unsigned long long c) {
    unsigned long long d;
    asm("fma.rn.f32x2 %0, %1, %2, %3;" : "=l"(d) : "l"(a), "l"(b), "l"(c));
    return d;
}
__device__ __forceinline__ float2 unpack2(unsigned long long v) {
    float lo, hi;
    asm("mov.b64 {%0, %1}, %2;" : "=f"(lo), "=f"(hi) : "l"(v));
    return make_float2(lo, hi);
}

__global__ __launch_bounds__(NTHREADS, 2)
void quanv_fused_kernel(const float* __restrict__ x,
                        const float* __restrict__ params,
                        const float* __restrict__ w,
                        const float* __restrict__ bias,
                        float* __restrict__ out,
                        int B, int depth)
{
    extern __shared__ float sm[];
    float* wbuf = sm;                 // [784][20]
    float* xstg = sm + WBUF_F;        // [16][8][36]
    __shared__ float ab[8];           // ab[q]=beta_q (cos), ab[4+q]=alpha_q (sin)

    const int tid   = threadIdx.x;
    const int lane  = tid & 31;
    const int chunk = tid >> 5;

    // ---- Phase 0: alpha/beta per qubit via exact 2x2 complex simulation ----
    if (tid < 8) {
        const int q     = tid & 3;
        const int which = tid >> 2;
        float ar = which ? 0.70710678118654752f : 1.0f, ai = 0.0f;
        float br = which ? 0.70710678118654752f : 0.0f, bi = 0.0f;
        for (int d = 0; d < depth; d++) {
            const float rz1 = params[d * 12 + q * 3 + 0];
            const float ry  = params[d * 12 + q * 3 + 1];
            const float rz2 = params[d * 12 + q * 3 + 2];
            float p1i, p1r; __sincosf(0.5f * rz1, &p1i, &p1r); p1i = -p1i;
            float nar = ar * p1r - ai * p1i, nai = ar * p1i + ai * p1r;
            float nbr = br * p1r + bi * p1i, nbi = bi * p1r - br * p1i;
            ar = nar; ai = nai; br = nbr; bi = nbi;
            float s, c; __sincosf(0.5f * ry, &s, &c);
            nar = c * ar - s * br; nai = c * ai - s * bi;
            nbr = s * ar + c * br; nbi = s * ai + c * bi;
            ar = nar; ai = nai; br = nbr; bi = nbi;
            float p2i, p2r; __sincosf(0.5f * rz2, &p2i, &p2r); p2i = -p2i;
            nar = ar * p2r - ai * p2i; nai = ar * p2i + ai * p2r;
            nbr = br * p2r + bi * p2i; nbi = bi * p2r - br * p2i;
            ar = nar; ai = nai; br = nbr; bi = nbi;
        }
        ab[which * 4 + q] = (ar * ar + ai * ai) - (br * br + bi * bi);
    }
    __syncthreads();

    // ---- Phase 1: fold w (patch-order) into pixel-order smem with alpha/beta ----
    for (int idx = tid; idx < NPIX * NCLS; idx += NTHREADS) {
        const int pix = idx / NCLS;
        const int c   = idx - pix * NCLS;
        const int r   = pix / 28;
        const int cc  = pix - r * 28;
        const int q   = ((r & 1) << 1) + (cc & 1);
        const int f   = (((r >> 1) * 14 + (cc >> 1)) << 2) + q;
        const float wv = w[c * NPIX + f];
        wbuf[pix * 20 + 2 * c]     = wv * ab[4 + q];  // sin coefficient
        wbuf[pix * 20 + 2 * c + 1] = wv * ab[q];      // cos coefficient
    }
    __syncthreads();

    // ---- Phase 2: main accumulation ----
    // warp = 32 images, chunk = 49 pixels. x staged in 8px x 32img tiles;
    // LDG: 4 images x 8 consecutive pixels per pass (4 full 32B sectors).
    const int b0   = blockIdx.x * TILE_B;
    const int bmax = B - 1 - b0;
    const int p0   = chunk * PPC;
    float* xsw = xstg + chunk * (TP * 36);

    const int sp = lane & 7;    // staging pixel within tile
    const int si = lane >> 3;   // staging image group offset

    unsigned long long acc[NCLS];
#pragma unroll
    for (int c = 0; c < NCLS; c++) acc[c] = 0ull;

    for (int t = 0; t < NTILE; t++) {
        const int tb = p0 + t * TP;
        // stage: xsw[pix][img], stride 36 -> conflict-free both directions
#pragma unroll
        for (int pass = 0; pass < 8; pass++) {
            int img = si + pass * 4;
            int ri = (img <= bmax) ? img : (bmax < 0 ? 0 : bmax);
            xsw[sp * 36 + img] = x[(size_t)(b0 + ri) * NPIX + tb + sp];
        }
        __syncwarp();
#pragma unroll 2
        for (int k = 0; k < TP; k++) {
            const float xv = xsw[k * 36 + lane];
            float s, co;
            __sincosf(xv, &s, &co);
            const unsigned long long sc = pack2(s, co);
            const ulonglong2* __restrict__ wp =
                reinterpret_cast<const ulonglong2*>(wbuf + (tb + k) * 20);
#pragma unroll
            for (int j = 0; j < 5; j++) {
                const ulonglong2 v = wp[j];
                acc[2 * j]     = ffma2(v.x, sc, acc[2 * j]);
                acc[2 * j + 1] = ffma2(v.y, sc, acc[2 * j + 1]);
            }
        }
        __syncwarp();
    }
    // leftover pixel (49 = 6*8 + 1): direct per-lane load
    {
        const int pix = p0 + 48;
        const int ri = (lane <= bmax) ? lane : (bmax < 0 ? 0 : bmax);
        const float xv = x[(size_t)(b0 + ri) * NPIX + pix];
        float s, co;
        __sincosf(xv, &s, &co);
        const unsigned long long sc = pack2(s, co);
        const ulonglong2* __restrict__ wp =
            reinterpret_cast<const ulonglong2*>(wbuf + pix * 20);
#pragma unroll
        for (int j = 0; j < 5; j++) {
            const ulonglong2 v = wp[j];
            acc[2 * j]     = ffma2(v.x, sc, acc[2 * j]);
            acc[2 * j + 1] = ffma2(v.y, sc, acc[2 * j + 1]);
        }
    }

    // ---- Phase 3: cross-chunk reduce + log-softmax (wbuf region reused) ----
    __syncthreads();                       // all warps done reading wbuf
    float* part = sm;                      // [16][32][10]
    float* red  = sm + NCHUNK * TILE_B * NCLS;  // [32][10]
    float* my = part + (chunk * TILE_B + lane) * NCLS;
#pragma unroll
    for (int c = 0; c < NCLS; c++) {
        const float2 f2 = unpack2(acc[c]);
        my[c] = f2.x + f2.y;
    }
    __syncthreads();

    if (tid < TILE_B * NCLS) {             // 320 threads: one (img, class) each
        const int img = tid / NCLS;
        const int c   = tid - img * NCLS;
        float sum = bias[c];
#pragma unroll
        for (int ch = 0; ch < NCHUNK; ch++)
            sum += part[(ch * TILE_B + img) * NCLS + c];
        red[img * NCLS + c] = sum;
    }
    __syncthreads();

    if (tid < TILE_B) {
        const int b2 = b0 + tid;
        if (b2 < B) {
            float l[NCLS];
#pragma unroll
            for (int c = 0; c < NCLS; c++) l[c] = red[tid * NCLS + c];
            float m = l[0];
#pragma unroll
            for (int c = 1; c < NCLS; c++) m = fmaxf(m, l[c]);
            float se = 0.0f;
#pragma unroll
            for (int c = 0; c < NCLS; c++) se += expf(l[c] - m);
            const float lse = m + logf(se);
            float* orow = out + (size_t)b2 * NCLS;
#pragma unroll
            for (int c = 0; c < NCLS; c++) orow[c] = l[c] - lse;
        }
    }
}

extern "C" void kernel_launch(void* const* d_in, const int* in_sizes, int n_in,
                              void* d_out, int out_size)
{
    const float* x      = (const float*)d_in[0];
    const float* params = (const float*)d_in[1];
    const float* w      = (const float*)d_in[2];
    const float* bias   = (const float*)d_in[3];
    float* out          = (float*)d_out;

    const int B     = in_sizes[0] / NPIX;
    const int depth = in_sizes[1] / 12;

    cudaFuncSetAttribute(quanv_fused_kernel,
                         cudaFuncAttributeMaxDynamicSharedMemorySize, SMEM_BYTES);

    const int grid = (B + TILE_B - 1) / TILE_B;
    quanv_fused_kernel<<<grid, NTHREADS, SMEM_BYTES>>>(x, params, w, bias, out, B, depth);
}